// round 10
// baseline (speedup 1.0000x reference)
#include <cuda_runtime.h>
#include <cuda_bf16.h>
#include <stdint.h>
#include <math.h>

#define B_ 4
#define N_ 4096
#define D_ 256
#define K_ 32
#define NC 40
#define INV_T 14.285714285714285714f

#define TILE_M 64
#define TILE_C 64                 // cols per tile
#define NCTILE 64                 // N_ / TILE_C
#define ROWB 512                  // bytes per feature row (256 bf16)
#define A_BYTES (TILE_M * ROWB)   // 32768
#define B_BYTES (TILE_C * ROWB)   // 32768

// smem: As @0 (32768) | Bs0 @32768 | Bs1 @65536 | total 98304
#define BS_OFF 32768
#define SMEM_TOTAL 98304

__device__ __nv_bfloat16 g_a[(size_t)B_ * N_ * D_];
__device__ __nv_bfloat16 g_b[(size_t)B_ * N_ * D_];
__device__ float g_f1n[(size_t)B_ * N_ * D_];
__device__ float g_f2n[(size_t)B_ * N_ * D_];

// ---------------------------------------------------------------------------
__device__ __forceinline__ uint32_t smem_u32(const void* p) {
    uint32_t a;
    asm("{ .reg .u64 t; cvta.to.shared.u64 t, %1; cvt.u32.u64 %0, t; }" : "=r"(a) : "l"(p));
    return a;
}
#define MBAR_INIT(a, c) asm volatile("mbarrier.init.shared.b64 [%0], %1;" :: "r"(a), "r"(c) : "memory")
#define MBAR_EXPECT(a, n) asm volatile("mbarrier.arrive.expect_tx.shared.b64 _, [%0], %1;" :: "r"(a), "r"(n) : "memory")
#define MBAR_WAIT(a, ph) do {                                                                 \
    uint32_t _m = (a); uint32_t _p = (ph); uint32_t _d;                                       \
    asm volatile("{ .reg .pred p; mbarrier.try_wait.parity.acquire.cta.shared::cta.b64 p, [%1], %2; selp.b32 %0,1,0,p; }" \
                 : "=r"(_d) : "r"(_m), "r"(_p) : "memory");                                   \
    while (!_d) {                                                                             \
        asm volatile("{ .reg .pred p; mbarrier.try_wait.parity.acquire.cta.shared::cta.b64 p, [%1], %2, 0x989680; selp.b32 %0,1,0,p; }" \
                     : "=r"(_d) : "r"(_m), "r"(_p) : "memory");                               \
    } } while (0)
#define FENCE_ASYNC() asm volatile("fence.proxy.async.shared::cta;" ::: "memory")

__device__ __forceinline__ void bulk_ld(uint32_t dst, const void* src, uint32_t bytes,
                                        uint32_t mbar) {
    asm volatile("cp.async.bulk.shared::cta.global.mbarrier::complete_tx::bytes [%0], [%1], %2, [%3];"
                 :: "r"(dst), "l"(src), "r"(bytes), "r"(mbar) : "memory");
}
__device__ __forceinline__ void ldsm4(uint32_t* r, uint32_t addr) {
    asm volatile("ldmatrix.sync.aligned.m8n8.x4.shared.b16 {%0,%1,%2,%3}, [%4];"
                 : "=r"(r[0]), "=r"(r[1]), "=r"(r[2]), "=r"(r[3]) : "r"(addr));
}
__device__ __forceinline__ void hmma(float* c, const uint32_t* a, const uint32_t* b) {
    asm volatile(
        "mma.sync.aligned.m16n8k16.row.col.f32.bf16.bf16.f32 "
        "{%0,%1,%2,%3}, {%4,%5,%6,%7}, {%8,%9}, {%0,%1,%2,%3};"
        : "+f"(c[0]), "+f"(c[1]), "+f"(c[2]), "+f"(c[3])
        : "r"(a[0]), "r"(a[1]), "r"(a[2]), "r"(a[3]), "r"(b[0]), "r"(b[1]));
}

// ---------------------------------------------------------------------------
// K1: normalize (fp32 division, like jax) + bf16 hi cast
// ---------------------------------------------------------------------------
__global__ void normalize_kernel(const float* __restrict__ F1,
                                 const float* __restrict__ F2) {
    int gw = (blockIdx.x * blockDim.x + threadIdx.x) >> 5;
    int lane = threadIdx.x & 31;
    const int R = B_ * N_;
    if (gw >= 2 * R) return;

    const float* src;
    __nv_bfloat16* dst;
    float* fdst;
    int row;
    if (gw < R) { src = F1; dst = g_a; fdst = g_f1n; row = gw; }
    else        { src = F2; dst = g_b; fdst = g_f2n; row = gw - R; }

    const float4* s4 = (const float4*)(src + (size_t)row * D_);
    float4 v0 = s4[lane];
    float4 v1 = s4[lane + 32];
    float ss = v0.x*v0.x + v0.y*v0.y + v0.z*v0.z + v0.w*v0.w
             + v1.x*v1.x + v1.y*v1.y + v1.z*v1.z + v1.w*v1.w;
#pragma unroll
    for (int o = 16; o; o >>= 1) ss += __shfl_xor_sync(0xffffffffu, ss, o);
    float nrm = fmaxf(sqrtf(ss), 1e-12f);

    float f[8] = {v0.x/nrm, v0.y/nrm, v0.z/nrm, v0.w/nrm,
                  v1.x/nrm, v1.y/nrm, v1.z/nrm, v1.w/nrm};

    float4* o4 = (float4*)(fdst + (size_t)row * D_);
    o4[lane]      = make_float4(f[0], f[1], f[2], f[3]);
    o4[lane + 32] = make_float4(f[4], f[5], f[6], f[7]);

    __nv_bfloat16* rp = dst + (size_t)row * D_;
#pragma unroll
    for (int i = 0; i < 8; i++) {
        int c = (i < 4) ? (lane * 4 + i) : (128 + lane * 4 + i - 4);
        rp[c] = __float2bfloat16_rn(f[i]);
    }
}

// ---------------------------------------------------------------------------
__device__ __forceinline__ void insert_cand(float* tv, int* ti, float v, int idx) {
    int pos = NC - 1;
    while (pos > 0 && tv[pos - 1] < v) {
        tv[pos] = tv[pos - 1];
        ti[pos] = ti[pos - 1];
        pos--;
    }
    tv[pos] = v;
    ti[pos] = idx;
}
__device__ __forceinline__ void insert_final(float* tv, int* ti, float v, int idx) {
    int pos = K_ - 1;
    while (pos > 0 && (tv[pos - 1] < v || (tv[pos - 1] == v && ti[pos - 1] > idx))) {
        tv[pos] = tv[pos - 1];
        ti[pos] = ti[pos - 1];
        pos--;
    }
    tv[pos] = v;
    ti[pos] = idx;
}

// ---------------------------------------------------------------------------
// fused: bulk-copy pipeline + HMMA + per-tile scan -> top-40 -> exact rescore
// grid (64, 4); 256 threads (8 warps: wm = wid&1 (32 rows), wn = wid>>1 (16 cols))
// ---------------------------------------------------------------------------
__global__ __launch_bounds__(256, 2) void gemm_topk_bulk(float* __restrict__ out) {
    extern __shared__ char smem[];
    __shared__ __align__(8) unsigned long long mbars[3];   // A, full0, full1

    const uint32_t sbase = smem_u32(smem);
    const uint32_t mbA  = smem_u32(&mbars[0]);
    const uint32_t mbF0 = smem_u32(&mbars[1]);
    const uint32_t mbF1 = smem_u32(&mbars[2]);

    const int tid  = threadIdx.x;
    const int wid  = tid >> 5;
    const int lane = tid & 31;
    const int wm   = wid & 1;
    const int wn   = wid >> 1;
    const int bb   = blockIdx.y;
    const int m0   = blockIdx.x * TILE_M;

    const char* gA = (const char*)g_a + ((size_t)(bb * N_ + m0)) * ROWB;
    const char* gB = (const char*)g_b + ((size_t)bb * N_) * ROWB;

    if (tid == 0) {
        MBAR_INIT(mbA, 1);
        MBAR_INIT(mbF0, 1);
        MBAR_INIT(mbF1, 1);
        FENCE_ASYNC();
        MBAR_EXPECT(mbA, A_BYTES);
        bulk_ld(sbase, gA, A_BYTES, mbA);
        MBAR_EXPECT(mbF0, B_BYTES);
        bulk_ld(sbase + BS_OFF, gB, B_BYTES, mbF0);
    }
    __syncthreads();
    MBAR_WAIT(mbA, 0);

    // ldmatrix lane addressing (non-swizzled [row][512B] layout)
    const int g  = lane >> 3;
    const int lr = lane & 7;
    const uint32_t arow = (uint32_t)(wm * 32 + (g & 1) * 8 + lr);
    const uint32_t acol = (uint32_t)((g >> 1) * 16);
    const uint32_t brow = (uint32_t)(wn * 16 + (g >> 1) * 8 + lr);
    const uint32_t bcol = (uint32_t)((g & 1) * 16);

    // scan state (thread-local lists, local memory)
    float tv[NC];
    int   ti[NC];
#pragma unroll
    for (int k = 0; k < NC; k++) { tv[k] = -3.4e38f; ti[k] = 0; }
    float tmin = -3.4e38f;
    const int srow = tid >> 1;       // scan row (tid < 128)
    const int shalf = tid & 1;

    for (int t = 0; t < NCTILE; ++t) {
        const uint32_t bbuf = sbase + BS_OFF + (t & 1) * B_BYTES;
        MBAR_WAIT((t & 1) ? mbF1 : mbF0, (t >> 1) & 1);
        __syncthreads();   // prior tile's scan (reads old buffer) complete

        if (tid == 0 && t + 1 < NCTILE) {
            const uint32_t nb = (t + 1) & 1;
            MBAR_EXPECT(nb ? mbF1 : mbF0, B_BYTES);
            bulk_ld(sbase + BS_OFF + nb * B_BYTES,
                    gB + (size_t)(t + 1) * TILE_C * ROWB, B_BYTES, nb ? mbF1 : mbF0);
        }

        float C[2][2][4];
#pragma unroll
        for (int mt = 0; mt < 2; mt++)
#pragma unroll
            for (int j = 0; j < 2; j++)
#pragma unroll
                for (int e = 0; e < 4; e++) C[mt][j][e] = 0.0f;

#pragma unroll
        for (int kc = 0; kc < 4; kc++) {
#pragma unroll
            for (int kk = 0; kk < 4; kk++) {
                const uint32_t koff = kc * 128 + kk * 32;
                uint32_t a0[4], a1[4], b[4];
                ldsm4(a0, sbase + arow * ROWB + koff + acol);
                ldsm4(a1, sbase + (arow + 16) * ROWB + koff + acol);
                ldsm4(b, bbuf + brow * ROWB + koff + bcol);
                hmma(C[0][0], a0, &b[0]);
                hmma(C[0][1], a0, &b[2]);
                hmma(C[1][0], a1, &b[0]);
                hmma(C[1][1], a1, &b[2]);
            }
        }
        __syncthreads();   // all mma reads of bbuf done before score dump

        // dump C into the consumed B buffer (rotated layout, 64x64 floats)
        float* scb = (float*)(smem + BS_OFF + (t & 1) * B_BYTES);
#pragma unroll
        for (int mt = 0; mt < 2; mt++) {
            const int r = wm * 32 + mt * 16 + (lane >> 2);
            const int c = wn * 16 + 2 * (lane & 3);
#pragma unroll
            for (int j = 0; j < 2; j++) {
                const int cc = c + j * 8;
                *(float2*)(scb + r * 64 + ((cc + 4 * r) & 63)) =
                    make_float2(C[mt][j][0], C[mt][j][1]);
                *(float2*)(scb + (r + 8) * 64 + ((cc + 4 * (r + 8)) & 63)) =
                    make_float2(C[mt][j][2], C[mt][j][3]);
            }
        }
        __syncthreads();

        // scan: 2 threads per row, 32 cols each
        if (tid < 128) {
            const float* base = scb + srow * 64;
            const int rot = 4 * srow;
#pragma unroll
            for (int grp = 0; grp < 2; grp++) {
                const int cb = shalf * 32 + grp * 16;
                float4 x0 = *(const float4*)(base + ((cb + 0  + rot) & 63));
                float4 x1 = *(const float4*)(base + ((cb + 4  + rot) & 63));
                float4 x2 = *(const float4*)(base + ((cb + 8  + rot) & 63));
                float4 x3 = *(const float4*)(base + ((cb + 12 + rot) & 63));
                float mx = fmaxf(fmaxf(fmaxf(x0.x, x0.y), fmaxf(x0.z, x0.w)),
                          fmaxf(fmaxf(fmaxf(x1.x, x1.y), fmaxf(x1.z, x1.w)),
                          fmaxf(fmaxf(fmaxf(x2.x, x2.y), fmaxf(x2.z, x2.w)),
                                fmaxf(fmaxf(x3.x, x3.y), fmaxf(x3.z, x3.w)))));
                if (mx > tmin) {
                    const int cg = t * 64 + cb;
                    float vals[16] = {x0.x, x0.y, x0.z, x0.w, x1.x, x1.y, x1.z, x1.w,
                                      x2.x, x2.y, x2.z, x2.w, x3.x, x3.y, x3.z, x3.w};
#pragma unroll
                    for (int j = 0; j < 16; j++) {
                        if (vals[j] > tmin) {
                            insert_cand(tv, ti, vals[j], cg + j);
                            tmin = tv[NC - 1];
                        }
                    }
                }
            }
        }
    }
    __syncthreads();

    // ---- dump per-half lists to smem scratch ----
    float* pv = (float*)smem;               // 128 * 40 floats = 20480B
    int*   pi = (int*)(smem + 20480);       // 128 * 40 ints   = 20480B
    if (tid < 128) {
#pragma unroll
        for (int k = 0; k < NC; k++) { pv[tid * NC + k] = tv[k]; pi[tid * NC + k] = ti[k]; }
    }
    __syncthreads();

    // ---- merge halves -> candidate lists ----
    float* cv = (float*)(smem + 40960);     // 64 * 40 floats
    int*   ci = (int*)(smem + 51200);       // 64 * 40 ints (ends 61440)
    if (tid < 64) {
        const float* v0 = pv + (2 * tid) * NC;
        const int*   i0 = pi + (2 * tid) * NC;
        const float* v1 = pv + (2 * tid + 1) * NC;
        const int*   i1 = pi + (2 * tid + 1) * NC;
        int a = 0, b2 = 0;
#pragma unroll
        for (int k = 0; k < NC; k++) {
            if (v0[a] >= v1[b2]) { cv[tid * NC + k] = v0[a]; ci[tid * NC + k] = i0[a]; a++; }
            else                 { cv[tid * NC + k] = v1[b2]; ci[tid * NC + k] = i1[b2]; b2++; }
        }
    }
    __syncthreads();

    // ---- exact fp32 rescore: warp per 8 rows ----
    {
        const float* f1b = g_f1n + ((size_t)(bb * N_ + m0)) * D_;
        const float* f2b = g_f2n + (size_t)bb * N_ * D_;
        for (int r = wid * 8; r < wid * 8 + 8; ++r) {
            const float4* a4 = (const float4*)(f1b + (size_t)r * D_);
            float4 a0 = a4[lane], a1 = a4[lane + 32];
#pragma unroll 2
            for (int c = 0; c < NC; ++c) {
                int col = ci[r * NC + c];
                const float4* b4 = (const float4*)(f2b + (size_t)col * D_);
                float4 b0 = b4[lane], b1 = b4[lane + 32];
                float s = a0.x * b0.x;
                s = fmaf(a0.y, b0.y, s);
                s = fmaf(a0.z, b0.z, s);
                s = fmaf(a0.w, b0.w, s);
                s = fmaf(a1.x, b1.x, s);
                s = fmaf(a1.y, b1.y, s);
                s = fmaf(a1.z, b1.z, s);
                s = fmaf(a1.w, b1.w, s);
#pragma unroll
                for (int o = 16; o; o >>= 1) s += __shfl_xor_sync(0xffffffffu, s, o);
                if (lane == 0) cv[r * NC + c] = s;
            }
        }
    }
    __syncthreads();

    // ---- final stable top-32 + softmax + scatter ----
    if (tid < TILE_M) {
        const int n = m0 + tid;
        float fv[K_];
        int fi[K_];
#pragma unroll
        for (int k = 0; k < K_; k++) { fv[k] = -3.4e38f; fi[k] = 0x7fffffff; }
#pragma unroll
        for (int c = 0; c < NC; c++) {
            float v = cv[tid * NC + c];
            int idx = ci[tid * NC + c];
            if (v > fv[K_ - 1] || (v == fv[K_ - 1] && idx < fi[K_ - 1]))
                insert_final(fv, fi, v, idx);
        }
        float mx = fv[0];
        float e[K_];
        float s = 0.0f;
#pragma unroll
        for (int k = 0; k < K_; k++) { e[k] = expf((fv[k] - mx) * INV_T); s += e[k]; }
        float inv = 1.0f / s;
        size_t rowbase = ((size_t)bb * N_ + n) * N_;
        size_t idxbase = (size_t)B_ * N_ * N_ + ((size_t)bb * N_ + n) * K_;
#pragma unroll
        for (int k = 0; k < K_; k++) {
            out[rowbase + (size_t)fi[k]] = e[k] * inv;
            out[idxbase + k] = (float)fi[k];
        }
    }
}

// ---------------------------------------------------------------------------
extern "C" void kernel_launch(void* const* d_in, const int* in_sizes, int n_in,
                              void* d_out, int out_size) {
    const float* F1 = (const float*)d_in[0];
    const float* F2 = (const float*)d_in[1];
    float* out = (float*)d_out;

    cudaMemsetAsync(out, 0, (size_t)B_ * N_ * N_ * sizeof(float), 0);
    normalize_kernel<<<4096, 256>>>(F1, F2);

    cudaFuncSetAttribute(gemm_topk_bulk,
                         cudaFuncAttributeMaxDynamicSharedMemorySize, SMEM_TOTAL);
    gemm_topk_bulk<<<dim3(N_ / TILE_M, B_), 256, SMEM_TOTAL>>>(out);
}

// round 13
// speedup vs baseline: 1.8632x; 1.8632x over previous
#include <cuda_runtime.h>
#include <cuda_bf16.h>
#include <stdint.h>
#include <math.h>

#define B_ 4
#define N_ 4096
#define D_ 256
#define K_ 32
#define NC 40
#define INV_T 14.285714285714285714f

#define TILE_M 128
#define TILE_N 128
#define NCTILE 32                // N_ / TILE_N
#define GS_TOTAL 128             // 32 tiles * 4 k-stages
#define SCP 132

// smem layout (bytes):
//   A resident : [0, 65536)            4 panels of 16KB (128 rows x 128B, swizzled)
//   B buffers  : [65536, 98304)        2 x 16KB
//   Sc         : [98304, 165888)       128 x 132 floats
// post-GEMM overlays:
//   pv: [0, 40960)  pi: [40960, 81920)  cv: [98304, 118784)  ci: [118784, 139264)
#define B_OFF 65536
#define SC_OFF 98304
#define PV_OFF 0
#define PI_OFF 40960
#define CV_OFF 98304
#define CI_OFF 118784
#define SMEM_TOTAL 165888

__device__ __nv_bfloat16 g_a[(size_t)B_ * N_ * D_];
__device__ __nv_bfloat16 g_b[(size_t)B_ * N_ * D_];
__device__ float g_f1n[(size_t)B_ * N_ * D_];
__device__ float g_f2n[(size_t)B_ * N_ * D_];

// ---------------------------------------------------------------------------
__device__ __forceinline__ uint32_t smem_u32(const void* p) {
    uint32_t a;
    asm("{ .reg .u64 t; cvta.to.shared.u64 t, %1; cvt.u32.u64 %0, t; }" : "=r"(a) : "l"(p));
    return a;
}
__device__ __forceinline__ uint32_t swz(uint32_t x) { return x ^ ((x >> 3) & 0x70); }

__device__ __forceinline__ void sts128(uint32_t addr, float4 v) {
    asm volatile("st.shared.v4.b32 [%0], {%1,%2,%3,%4};"
                 :: "r"(addr), "f"(v.x), "f"(v.y), "f"(v.z), "f"(v.w) : "memory");
}
__device__ __forceinline__ void ldsm4(uint32_t* r, uint32_t addr) {
    asm volatile("ldmatrix.sync.aligned.m8n8.x4.shared.b16 {%0,%1,%2,%3}, [%4];"
                 : "=r"(r[0]), "=r"(r[1]), "=r"(r[2]), "=r"(r[3]) : "r"(addr));
}
__device__ __forceinline__ void hmma(float* c, const uint32_t* a, const uint32_t* b) {
    asm volatile(
        "mma.sync.aligned.m16n8k16.row.col.f32.bf16.bf16.f32 "
        "{%0,%1,%2,%3}, {%4,%5,%6,%7}, {%8,%9}, {%0,%1,%2,%3};"
        : "+f"(c[0]), "+f"(c[1]), "+f"(c[2]), "+f"(c[3])
        : "r"(a[0]), "r"(a[1]), "r"(a[2]), "r"(a[3]), "r"(b[0]), "r"(b[1]));
}

// ---------------------------------------------------------------------------
// K1: normalize (fp32 division, like jax) + bf16 hi cast
// ---------------------------------------------------------------------------
__global__ void normalize_kernel(const float* __restrict__ F1,
                                 const float* __restrict__ F2) {
    int gw = (blockIdx.x * blockDim.x + threadIdx.x) >> 5;
    int lane = threadIdx.x & 31;
    const int R = B_ * N_;
    if (gw >= 2 * R) return;

    const float* src;
    __nv_bfloat16* dst;
    float* fdst;
    int row;
    if (gw < R) { src = F1; dst = g_a; fdst = g_f1n; row = gw; }
    else        { src = F2; dst = g_b; fdst = g_f2n; row = gw - R; }

    const float4* s4 = (const float4*)(src + (size_t)row * D_);
    float4 v0 = s4[lane];
    float4 v1 = s4[lane + 32];
    float ss = v0.x*v0.x + v0.y*v0.y + v0.z*v0.z + v0.w*v0.w
             + v1.x*v1.x + v1.y*v1.y + v1.z*v1.z + v1.w*v1.w;
#pragma unroll
    for (int o = 16; o; o >>= 1) ss += __shfl_xor_sync(0xffffffffu, ss, o);
    float nrm = fmaxf(sqrtf(ss), 1e-12f);

    float f[8] = {v0.x/nrm, v0.y/nrm, v0.z/nrm, v0.w/nrm,
                  v1.x/nrm, v1.y/nrm, v1.z/nrm, v1.w/nrm};

    float4* o4 = (float4*)(fdst + (size_t)row * D_);
    o4[lane]      = make_float4(f[0], f[1], f[2], f[3]);
    o4[lane + 32] = make_float4(f[4], f[5], f[6], f[7]);

    __nv_bfloat16* rp = dst + (size_t)row * D_;
#pragma unroll
    for (int i = 0; i < 8; i++) {
        int c = (i < 4) ? (lane * 4 + i) : (128 + lane * 4 + i - 4);
        rp[c] = __float2bfloat16_rn(f[i]);
    }
}

// ---------------------------------------------------------------------------
__device__ __forceinline__ void insert_cand(float* tv, int* ti, float v, int idx) {
    int pos = NC - 1;
    while (pos > 0 && tv[pos - 1] < v) {
        tv[pos] = tv[pos - 1];
        ti[pos] = ti[pos - 1];
        pos--;
    }
    tv[pos] = v;
    ti[pos] = idx;
}
__device__ __forceinline__ void insert_final(float* tv, int* ti, float v, int idx) {
    int pos = K_ - 1;
    while (pos > 0 && (tv[pos - 1] < v || (tv[pos - 1] == v && ti[pos - 1] > idx))) {
        tv[pos] = tv[pos - 1];
        ti[pos] = ti[pos - 1];
        pos--;
    }
    tv[pos] = v;
    ti[pos] = idx;
}

// ---------------------------------------------------------------------------
// fused: LDG->STS pipeline + HMMA + per-tile scan -> top-40 -> exact rescore
// grid (32, 4); 512 threads (16 warps: 4m x 4n), warp tile 32x32
// ---------------------------------------------------------------------------
__global__ __launch_bounds__(512, 1) void gemm_topk_ldg(float* __restrict__ out) {
    extern __shared__ char smem[];
    const uint32_t sbase = smem_u32(smem);
    float* Sc = (float*)(smem + SC_OFF);

    const int tid  = threadIdx.x;
    const int wid  = tid >> 5;
    const int lane = tid & 31;
    const int wm   = wid & 3;
    const int wn   = wid >> 2;
    const int bb   = blockIdx.y;
    const int m0   = blockIdx.x * TILE_M;

    const char* gA = (const char*)g_a + ((size_t)(bb * N_ + m0)) * 512;
    const char* gB = (const char*)g_b + ((size_t)bb * N_) * 512;

    // ---- load A resident (4 panels of 16KB, swizzled 128B rows) ----
#pragma unroll
    for (int i = 0; i < 8; i++) {
        int ch = i * 512 + tid;            // 4096 chunks
        int r = ch >> 5, cc = ch & 31;
        float4 v = *(const float4*)(gA + (size_t)r * 512 + cc * 16);
        sts128(sbase + (cc >> 3) * 16384 + swz(r * 128 + (cc & 7) * 16), v);
    }

    // ldmatrix lane addressing
    const int g  = lane >> 3;
    const int lr = lane & 7;
    const uint32_t aoff = (uint32_t)((wm * 32 + (g & 1) * 8 + lr) * 128 + (g >> 1) * 16);
    const uint32_t boff = (uint32_t)((wn * 32 + (g >> 1) * 8 + lr) * 128 + (g & 1) * 16);

    // ---- B stage loads: 1024 chunks / 512 thr = 2 per thread ----
    // chunk ch: r = ch>>3 (row), c = ch&7 (16B col)
    const int ch0 = tid, ch1 = tid + 512;
    const int r0c = ch0 >> 3, c0c = ch0 & 7;
    const int r1c = ch1 >> 3, c1c = ch1 & 7;
    const uint32_t d0 = swz(r0c * 128 + c0c * 16);
    const uint32_t d1 = swz(r1c * 128 + c1c * 16);

    float4 rb0, rb1;
    // prologue: stage 0 (tile 0, k-slice 0)
    rb0 = *(const float4*)(gB + (size_t)r0c * 512 + 0 * 128 + c0c * 16);
    rb1 = *(const float4*)(gB + (size_t)r1c * 512 + 0 * 128 + c1c * 16);
    sts128(sbase + B_OFF + d0, rb0);
    sts128(sbase + B_OFF + d1, rb1);
    __syncthreads();

    // scan state
    float tv[NC];
    int   ti[NC];
#pragma unroll
    for (int k = 0; k < NC; k++) { tv[k] = -3.4e38f; ti[k] = 0; }
    float tmin = -3.4e38f;
    const int srow  = tid >> 1;
    const int shalf = tid & 1;

    float C[2][4][4];
#pragma unroll
    for (int mt = 0; mt < 2; mt++)
#pragma unroll
        for (int nt = 0; nt < 4; nt++)
#pragma unroll
            for (int e = 0; e < 4; e++) C[mt][nt][e] = 0.0f;

    for (int gs = 0; gs < GS_TOTAL; ++gs) {
        // prefetch next stage into registers (a full stage early)
        if (gs + 1 < GS_TOTAL) {
            const int nt_ = (gs + 1) >> 2;
            const int ns_ = (gs + 1) & 3;
            const char* src = gB + (size_t)nt_ * TILE_N * 512 + ns_ * 128;
            rb0 = *(const float4*)(src + (size_t)r0c * 512 + c0c * 16);
            rb1 = *(const float4*)(src + (size_t)r1c * 512 + c1c * 16);
        }

        // mma on buffer gs&1, A panel gs&3
        const uint32_t sA = sbase + (gs & 3) * 16384;
        const uint32_t sB = sbase + B_OFF + (gs & 1) * 16384;
#pragma unroll
        for (int kk = 0; kk < 4; kk++) {
            const uint32_t koff = kk * 32;
            uint32_t a0[4], a1[4], b[2][4];
            ldsm4(a0, sA + swz(aoff + koff));
            ldsm4(a1, sA + swz(aoff + 2048 + koff));
            ldsm4(b[0], sB + swz(boff + koff));
            ldsm4(b[1], sB + swz(boff + 2048 + koff));
#pragma unroll
            for (int p = 0; p < 2; p++) {
                hmma(C[0][2 * p + 0], a0, &b[p][0]);
                hmma(C[0][2 * p + 1], a0, &b[p][2]);
                hmma(C[1][2 * p + 0], a1, &b[p][0]);
                hmma(C[1][2 * p + 1], a1, &b[p][2]);
            }
        }

        if ((gs & 3) == 3) {
            // dump tile scores + scan
            const int t = gs >> 2;
            __syncthreads();
#pragma unroll
            for (int mt = 0; mt < 2; mt++) {
                const int r = wm * 32 + mt * 16 + (lane >> 2);
                const int c0 = wn * 32 + 2 * (lane & 3);
#pragma unroll
                for (int nt = 0; nt < 4; nt++) {
                    const int c = c0 + nt * 8;
                    *(float2*)(Sc + r * SCP + c) = make_float2(C[mt][nt][0], C[mt][nt][1]);
                    *(float2*)(Sc + (r + 8) * SCP + c) = make_float2(C[mt][nt][2], C[mt][nt][3]);
                }
            }
            __syncthreads();

            if (tid < 256) {
                const float* sr = Sc + srow * SCP + shalf * 64;
#pragma unroll
                for (int grp = 0; grp < 4; grp++) {
                    float4 x0 = *(const float4*)(sr + grp * 16 + 0);
                    float4 x1 = *(const float4*)(sr + grp * 16 + 4);
                    float4 x2 = *(const float4*)(sr + grp * 16 + 8);
                    float4 x3 = *(const float4*)(sr + grp * 16 + 12);
                    float mx = fmaxf(fmaxf(fmaxf(x0.x, x0.y), fmaxf(x0.z, x0.w)),
                              fmaxf(fmaxf(fmaxf(x1.x, x1.y), fmaxf(x1.z, x1.w)),
                              fmaxf(fmaxf(fmaxf(x2.x, x2.y), fmaxf(x2.z, x2.w)),
                                    fmaxf(fmaxf(x3.x, x3.y), fmaxf(x3.z, x3.w)))));
                    if (mx > tmin) {
                        const int cg = t * TILE_N + shalf * 64 + grp * 16;
                        float vals[16] = {x0.x, x0.y, x0.z, x0.w, x1.x, x1.y, x1.z, x1.w,
                                          x2.x, x2.y, x2.z, x2.w, x3.x, x3.y, x3.z, x3.w};
#pragma unroll
                        for (int j = 0; j < 16; j++) {
                            if (vals[j] > tmin) {
                                insert_cand(tv, ti, vals[j], cg + j);
                                tmin = tv[NC - 1];
                            }
                        }
                    }
                }
            }
            // re-zero accumulators
#pragma unroll
            for (int mt = 0; mt < 2; mt++)
#pragma unroll
                for (int nt = 0; nt < 4; nt++)
#pragma unroll
                    for (int e = 0; e < 4; e++) C[mt][nt][e] = 0.0f;
        }

        __syncthreads();   // all reads of buf (gs+1)&1 from stage gs-1 done
        if (gs + 1 < GS_TOTAL) {
            const uint32_t nb = sbase + B_OFF + ((gs + 1) & 1) * 16384;
            sts128(nb + d0, rb0);
            sts128(nb + d1, rb1);
            __syncthreads();
        }
    }
    __syncthreads();

    // ---- dump per-half lists ----
    float* pv = (float*)(smem + PV_OFF);
    int*   pi = (int*)(smem + PI_OFF);
    if (tid < 256) {
#pragma unroll
        for (int k = 0; k < NC; k++) { pv[tid * NC + k] = tv[k]; pi[tid * NC + k] = ti[k]; }
    }
    __syncthreads();

    // ---- merge halves -> per-row candidate lists ----
    float* cv = (float*)(smem + CV_OFF);
    int*   ci = (int*)(smem + CI_OFF);
    if (tid < TILE_M) {
        const float* v0 = pv + (2 * tid) * NC;
        const int*   i0 = pi + (2 * tid) * NC;
        const float* v1 = pv + (2 * tid + 1) * NC;
        const int*   i1 = pi + (2 * tid + 1) * NC;
        int a = 0, b2 = 0;
#pragma unroll
        for (int k = 0; k < NC; k++) {
            if (v0[a] >= v1[b2]) { cv[tid * NC + k] = v0[a]; ci[tid * NC + k] = i0[a]; a++; }
            else                 { cv[tid * NC + k] = v1[b2]; ci[tid * NC + k] = i1[b2]; b2++; }
        }
    }
    __syncthreads();

    // ---- exact fp32 rescore: warp per 8 rows ----
    {
        const float* f1b = g_f1n + ((size_t)(bb * N_ + m0)) * D_;
        const float* f2b = g_f2n + (size_t)bb * N_ * D_;
        for (int r = wid * 8; r < wid * 8 + 8; ++r) {
            const float4* a4 = (const float4*)(f1b + (size_t)r * D_);
            float4 a0 = a4[lane], a1 = a4[lane + 32];
#pragma unroll 2
            for (int c = 0; c < NC; ++c) {
                int col = ci[r * NC + c];
                const float4* b4 = (const float4*)(f2b + (size_t)col * D_);
                float4 b0 = b4[lane], b1 = b4[lane + 32];
                float s = a0.x * b0.x;
                s = fmaf(a0.y, b0.y, s);
                s = fmaf(a0.z, b0.z, s);
                s = fmaf(a0.w, b0.w, s);
                s = fmaf(a1.x, b1.x, s);
                s = fmaf(a1.y, b1.y, s);
                s = fmaf(a1.z, b1.z, s);
                s = fmaf(a1.w, b1.w, s);
#pragma unroll
                for (int o = 16; o; o >>= 1) s += __shfl_xor_sync(0xffffffffu, s, o);
                if (lane == 0) cv[r * NC + c] = s;
            }
        }
    }
    __syncthreads();

    // ---- final stable top-32 + softmax + scatter ----
    if (tid < TILE_M) {
        const int n = m0 + tid;
        float fv[K_];
        int fi[K_];
#pragma unroll
        for (int k = 0; k < K_; k++) { fv[k] = -3.4e38f; fi[k] = 0x7fffffff; }
#pragma unroll
        for (int c = 0; c < NC; c++) {
            float v = cv[tid * NC + c];
            int idx = ci[tid * NC + c];
            if (v > fv[K_ - 1] || (v == fv[K_ - 1] && idx < fi[K_ - 1]))
                insert_final(fv, fi, v, idx);
        }
        float mx = fv[0];
        float e[K_];
        float s = 0.0f;
#pragma unroll
        for (int k = 0; k < K_; k++) { e[k] = expf((fv[k] - mx) * INV_T); s += e[k]; }
        float inv = 1.0f / s;
        size_t rowbase = ((size_t)bb * N_ + n) * N_;
        size_t idxbase = (size_t)B_ * N_ * N_ + ((size_t)bb * N_ + n) * K_;
#pragma unroll
        for (int k = 0; k < K_; k++) {
            out[rowbase + (size_t)fi[k]] = e[k] * inv;
            out[idxbase + k] = (float)fi[k];
        }
    }
}

// ---------------------------------------------------------------------------
extern "C" void kernel_launch(void* const* d_in, const int* in_sizes, int n_in,
                              void* d_out, int out_size) {
    const float* F1 = (const float*)d_in[0];
    const float* F2 = (const float*)d_in[1];
    float* out = (float*)d_out;

    cudaMemsetAsync(out, 0, (size_t)B_ * N_ * N_ * sizeof(float), 0);
    normalize_kernel<<<4096, 256>>>(F1, F2);

    cudaFuncSetAttribute(gemm_topk_ldg,
                         cudaFuncAttributeMaxDynamicSharedMemorySize, SMEM_TOTAL);
    gemm_topk_ldg<<<dim3(NCTILE, B_), 512, SMEM_TOTAL>>>(out);
}

// round 16
// speedup vs baseline: 3.8996x; 2.0929x over previous
#include <cuda_runtime.h>
#include <stdint.h>
#include <math.h>

#define B_ 4
#define N_ 4096
#define D_ 256
#define K_ 32
#define NC 40
#define INV_T 14.285714285714285714f

#define TILE_M 128
#define TILE_N 128
#define NCTILE 32            // N_/TILE_N
#define NSTAGE 256           // 32 tiles * 8 k-chunks of 32
#define ASP2 268             // duplicated A row: 256 floats + pad
#define BSP 132
#define SCP 132

// smem float offsets
#define AS0 0                // 32*268 = 8576
#define AS1 8576
#define BS0 17152            // 32*132 = 4224
#define BS1 21376
#define SC  25600            // 128*132 = 16896
#define TV  42496            // 128*40 = 5120
#define TI  47616            // 128*40 = 5120
#define SMEM_TOTAL (52736 * 4)   // 210944 bytes

__device__ float g_f1n[(size_t)B_ * N_ * D_];
__device__ float g_f2n[(size_t)B_ * N_ * D_];

// ---------------------------------------------------------------------------
__device__ __forceinline__ unsigned long long ffma2(unsigned long long a,
                                                    unsigned long long b,
                                                    unsigned long long c) {
    unsigned long long d;
    asm("fma.rn.f32x2 %0, %1, %2, %3;" : "=l"(d) : "l"(a), "l"(b), "l"(c));
    return d;
}

// ---------------------------------------------------------------------------
// K1: normalize (fp32 division, like jax)
// ---------------------------------------------------------------------------
__global__ void normalize_kernel(const float* __restrict__ F1,
                                 const float* __restrict__ F2) {
    int gw = (blockIdx.x * blockDim.x + threadIdx.x) >> 5;
    int lane = threadIdx.x & 31;
    const int R = B_ * N_;
    if (gw >= 2 * R) return;

    const float* src;
    float* fdst;
    int row;
    if (gw < R) { src = F1; fdst = g_f1n; row = gw; }
    else        { src = F2; fdst = g_f2n; row = gw - R; }

    const float4* s4 = (const float4*)(src + (size_t)row * D_);
    float4 v0 = s4[lane];
    float4 v1 = s4[lane + 32];
    float ss = v0.x*v0.x + v0.y*v0.y + v0.z*v0.z + v0.w*v0.w
             + v1.x*v1.x + v1.y*v1.y + v1.z*v1.z + v1.w*v1.w;
#pragma unroll
    for (int o = 16; o; o >>= 1) ss += __shfl_xor_sync(0xffffffffu, ss, o);
    float nrm = fmaxf(sqrtf(ss), 1e-12f);

    float4* o4 = (float4*)(fdst + (size_t)row * D_);
    o4[lane]      = make_float4(v0.x/nrm, v0.y/nrm, v0.z/nrm, v0.w/nrm);
    o4[lane + 32] = make_float4(v1.x/nrm, v1.y/nrm, v1.z/nrm, v1.w/nrm);
}

// ---------------------------------------------------------------------------
// candidate insert (sorted desc, strict > keeps lower index first on ties)
// ---------------------------------------------------------------------------
__device__ __forceinline__ void insert_cand(float* tv, int* ti, float v, int idx) {
    int pos = NC - 1;
    while (pos > 0 && tv[pos - 1] < v) {
        tv[pos] = tv[pos - 1];
        ti[pos] = ti[pos - 1];
        pos--;
    }
    tv[pos] = v;
    ti[pos] = idx;
}
// final stable top-K insert: desc value, ascending index on exact ties (jax)
__device__ __forceinline__ void insert_final(float* tv, int* ti, float v, int idx) {
    int pos = K_ - 1;
    while (pos > 0 && (tv[pos - 1] < v || (tv[pos - 1] == v && ti[pos - 1] > idx))) {
        tv[pos] = tv[pos - 1];
        ti[pos] = ti[pos - 1];
        pos--;
    }
    tv[pos] = v;
    ti[pos] = idx;
}

// ---------------------------------------------------------------------------
// fused exact-fp32 FFMA2 GEMM + top-40 candidates + tree-rescore + top-32
// grid (32, 4); 512 threads: ty = tid>>5 (8-row group), tx = tid&31 (4-col group)
// ---------------------------------------------------------------------------
__global__ __launch_bounds__(512, 1) void sgemm_topk(float* __restrict__ out) {
    extern __shared__ float sm[];

    const int tid = threadIdx.x;
    const int wid = tid >> 5;
    const int lane = tid & 31;
    const int ty  = wid;               // 0..15
    const int tx  = lane;              // 0..31
    const int bb  = blockIdx.y;
    const int m0  = blockIdx.x * TILE_M;

    // loader mapping: 1024 float4 per chunk, 2 per thread
    const int lr0 = tid >> 3;          // 0..63
    const int lr1 = lr0 + 64;          // 64..127
    const int kq  = tid & 7;           // float4 within 32-k slice

    const float4* Aabs = (const float4*)(g_f1n + ((size_t)(bb * N_ + m0)) * D_);
    const float4* Babs = (const float4*)(g_f2n + ((size_t)bb * N_) * D_);

    // init candidate lists
    if (tid < TILE_M) {
        float* tv = sm + TV + tid * NC;
        int*   ti = (int*)(sm + TI) + tid * NC;
#pragma unroll
        for (int k = 0; k < NC; k++) { tv[k] = -3.4e38f; ti[k] = 0; }
    }

    // prologue: stage 0 (tile 0, kc 0)
    float4 pa0 = Aabs[lr0 * 64 + kq];
    float4 pa1 = Aabs[lr1 * 64 + kq];
    float4 pb0 = Babs[lr0 * 64 + kq];
    float4 pb1 = Babs[lr1 * 64 + kq];
    {
        float* as = sm + AS0;
        float* bs = sm + BS0;
        const float va0[4] = {pa0.x, pa0.y, pa0.z, pa0.w};
        const float va1[4] = {pa1.x, pa1.y, pa1.z, pa1.w};
        const float vb0[4] = {pb0.x, pb0.y, pb0.z, pb0.w};
        const float vb1[4] = {pb1.x, pb1.y, pb1.z, pb1.w};
#pragma unroll
        for (int e = 0; e < 4; e++) {
            *(float2*)(as + (kq * 4 + e) * ASP2 + 2 * lr0) = make_float2(va0[e], va0[e]);
            *(float2*)(as + (kq * 4 + e) * ASP2 + 2 * lr1) = make_float2(va1[e], va1[e]);
            bs[(kq * 4 + e) * BSP + lr0] = vb0[e];
            bs[(kq * 4 + e) * BSP + lr1] = vb1[e];
        }
    }
    __syncthreads();

    unsigned long long c[8][2];
#pragma unroll
    for (int i = 0; i < 8; i++) { c[i][0] = 0ull; c[i][1] = 0ull; }

    const int arow = 16 * ty;
    const int bcol = tx * 4;

#pragma unroll 1
    for (int s = 0; s < NSTAGE; ++s) {
        // prefetch next stage
        if (s + 1 < NSTAGE) {
            const int sn = s + 1;
            const int tn = sn >> 3, kcn = sn & 7;
            pa0 = Aabs[lr0 * 64 + kcn * 8 + kq];
            pa1 = Aabs[lr1 * 64 + kcn * 8 + kq];
            pb0 = Babs[(tn * TILE_N + lr0) * 64 + kcn * 8 + kq];
            pb1 = Babs[(tn * TILE_N + lr1) * 64 + kcn * 8 + kq];
        }

        const float* as = sm + ((s & 1) ? AS1 : AS0);
        const float* bs = sm + ((s & 1) ? BS1 : BS0);
#pragma unroll
        for (int kk = 0; kk < 32; ++kk) {
            const float* ar = as + kk * ASP2 + arow;
            const float* br = bs + kk * BSP + bcol;
            ulonglong2 A01 = *(const ulonglong2*)(ar);
            ulonglong2 A23 = *(const ulonglong2*)(ar + 4);
            ulonglong2 A45 = *(const ulonglong2*)(ar + 8);
            ulonglong2 A67 = *(const ulonglong2*)(ar + 12);
            ulonglong2 Bp  = *(const ulonglong2*)(br);
            c[0][0] = ffma2(A01.x, Bp.x, c[0][0]);
            c[0][1] = ffma2(A01.x, Bp.y, c[0][1]);
            c[1][0] = ffma2(A01.y, Bp.x, c[1][0]);
            c[1][1] = ffma2(A01.y, Bp.y, c[1][1]);
            c[2][0] = ffma2(A23.x, Bp.x, c[2][0]);
            c[2][1] = ffma2(A23.x, Bp.y, c[2][1]);
            c[3][0] = ffma2(A23.y, Bp.x, c[3][0]);
            c[3][1] = ffma2(A23.y, Bp.y, c[3][1]);
            c[4][0] = ffma2(A45.x, Bp.x, c[4][0]);
            c[4][1] = ffma2(A45.x, Bp.y, c[4][1]);
            c[5][0] = ffma2(A45.y, Bp.x, c[5][0]);
            c[5][1] = ffma2(A45.y, Bp.y, c[5][1]);
            c[6][0] = ffma2(A67.x, Bp.x, c[6][0]);
            c[6][1] = ffma2(A67.x, Bp.y, c[6][1]);
            c[7][0] = ffma2(A67.y, Bp.x, c[7][0]);
            c[7][1] = ffma2(A67.y, Bp.y, c[7][1]);
        }

        const int tile_end = ((s & 7) == 7);
        if (tile_end) {
#pragma unroll
            for (int i = 0; i < 8; i++) {
                *(ulonglong2*)(sm + SC + (ty * 8 + i) * SCP + tx * 4) =
                    make_ulonglong2(c[i][0], c[i][1]);
                c[i][0] = 0ull;
                c[i][1] = 0ull;
            }
        }

        if (s + 1 < NSTAGE) {
            float* asn = sm + (((s + 1) & 1) ? AS1 : AS0);
            float* bsn = sm + (((s + 1) & 1) ? BS1 : BS0);
            const float va0[4] = {pa0.x, pa0.y, pa0.z, pa0.w};
            const float va1[4] = {pa1.x, pa1.y, pa1.z, pa1.w};
            const float vb0[4] = {pb0.x, pb0.y, pb0.z, pb0.w};
            const float vb1[4] = {pb1.x, pb1.y, pb1.z, pb1.w};
#pragma unroll
            for (int e = 0; e < 4; e++) {
                *(float2*)(asn + (kq * 4 + e) * ASP2 + 2 * lr0) = make_float2(va0[e], va0[e]);
                *(float2*)(asn + (kq * 4 + e) * ASP2 + 2 * lr1) = make_float2(va1[e], va1[e]);
                bsn[(kq * 4 + e) * BSP + lr0] = vb0[e];
                bsn[(kq * 4 + e) * BSP + lr1] = vb1[e];
            }
        }
        __syncthreads();

        // scan the dumped tile into top-40 candidate lists
        if (tile_end && tid < TILE_M) {
            const int t = s >> 3;
            const int cb = t * TILE_N;
            float* tv = sm + TV + tid * NC;
            int*   ti = (int*)(sm + TI) + tid * NC;
            const float* sr = sm + SC + tid * SCP;
            float tmin = tv[NC - 1];
#pragma unroll 4
            for (int j = 0; j < TILE_N; j += 4) {
                float4 x = *(const float4*)(sr + j);
                float mx = fmaxf(fmaxf(x.x, x.y), fmaxf(x.z, x.w));
                if (mx > tmin) {
                    if (x.x > tmin) { insert_cand(tv, ti, x.x, cb + j + 0); tmin = tv[NC - 1]; }
                    if (x.y > tmin) { insert_cand(tv, ti, x.y, cb + j + 1); tmin = tv[NC - 1]; }
                    if (x.z > tmin) { insert_cand(tv, ti, x.z, cb + j + 2); tmin = tv[NC - 1]; }
                    if (x.w > tmin) { insert_cand(tv, ti, x.w, cb + j + 3); tmin = tv[NC - 1]; }
                }
            }
        }
    }
    __syncthreads();

    // ---- exact fp32 rescore (warp-tree order = R7/R8 proven): warp/8 rows ----
    {
        float* cv = sm + TV;
        int*   ci = (int*)(sm + TI);
        const float* f1b = g_f1n + ((size_t)(bb * N_ + m0)) * D_;
        const float* f2b = g_f2n + (size_t)bb * N_ * D_;
        for (int r = wid * 8; r < wid * 8 + 8; ++r) {
            const float4* a4 = (const float4*)(f1b + (size_t)r * D_);
            float4 a0 = a4[lane], a1 = a4[lane + 32];
#pragma unroll 2
            for (int cdx = 0; cdx < NC; ++cdx) {
                int col = ci[r * NC + cdx];
                const float4* b4 = (const float4*)(f2b + (size_t)col * D_);
                float4 b0 = b4[lane], b1 = b4[lane + 32];
                float sv = a0.x * b0.x;
                sv = fmaf(a0.y, b0.y, sv);
                sv = fmaf(a0.z, b0.z, sv);
                sv = fmaf(a0.w, b0.w, sv);
                sv = fmaf(a1.x, b1.x, sv);
                sv = fmaf(a1.y, b1.y, sv);
                sv = fmaf(a1.z, b1.z, sv);
                sv = fmaf(a1.w, b1.w, sv);
#pragma unroll
                for (int o = 16; o; o >>= 1) sv += __shfl_xor_sync(0xffffffffu, sv, o);
                if (lane == 0) cv[r * NC + cdx] = sv;
            }
        }
    }
    __syncthreads();

    // ---- final stable top-32 + softmax + scatter ----
    if (tid < TILE_M) {
        const int n = m0 + tid;
        const float* cv = sm + TV + tid * NC;
        const int*   ci = (int*)(sm + TI) + tid * NC;
        float fv[K_];
        int fi[K_];
#pragma unroll
        for (int k = 0; k < K_; k++) { fv[k] = -3.4e38f; fi[k] = 0x7fffffff; }
#pragma unroll
        for (int cdx = 0; cdx < NC; cdx++) {
            float v = cv[cdx];
            int idx = ci[cdx];
            if (v > fv[K_ - 1] || (v == fv[K_ - 1] && idx < fi[K_ - 1]))
                insert_final(fv, fi, v, idx);
        }
        float mx = fv[0];
        float e[K_];
        float ssum = 0.0f;
#pragma unroll
        for (int k = 0; k < K_; k++) { e[k] = expf((fv[k] - mx) * INV_T); ssum += e[k]; }
        float inv = 1.0f / ssum;
        size_t rowbase = ((size_t)bb * N_ + n) * N_;
        size_t idxbase = (size_t)B_ * N_ * N_ + ((size_t)bb * N_ + n) * K_;
#pragma unroll
        for (int k = 0; k < K_; k++) {
            out[rowbase + (size_t)fi[k]] = e[k] * inv;
            out[idxbase + k] = (float)fi[k];
        }
    }
}

// ---------------------------------------------------------------------------
extern "C" void kernel_launch(void* const* d_in, const int* in_sizes, int n_in,
                              void* d_out, int out_size) {
    const float* F1 = (const float*)d_in[0];
    const float* F2 = (const float*)d_in[1];
    float* out = (float*)d_out;

    cudaMemsetAsync(out, 0, (size_t)B_ * N_ * N_ * sizeof(float), 0);
    normalize_kernel<<<4096, 256>>>(F1, F2);

    cudaFuncSetAttribute(sgemm_topk,
                         cudaFuncAttributeMaxDynamicSharedMemorySize, SMEM_TOTAL);
    sgemm_topk<<<dim3(NCTILE, B_), 512, SMEM_TOTAL>>>(out);
}